// round 6
// baseline (speedup 1.0000x reference)
#include <cuda_runtime.h>

#define C_   128
#define H_   128
#define W_   256
#define B_   8
#define KS   9
#define PAD  4
#define TCO  16                        // co per block = 8 co-pairs
#define CPB  8                         // co-pairs per block
#define CI_CHUNK 32
#define WPS  (CI_CHUNK*20 + 4)         // 644 floats per co-pair row; 644%32=4 -> conflict-free
#define STRIDE_C (H_*W_)

__device__ float g_yt[(size_t)B_ * C_ * H_ * W_];     // transposed tensor scratch
__device__ float g_wpair[4 * 64 * C_ * 20];           // interleaved co-pair weights, 2.6 MB

// ---- f32x2 helpers ----
__device__ __forceinline__ unsigned long long pk2(float v) {
    unsigned long long r;
    asm("mov.b64 %0, {%1, %1};" : "=l"(r) : "f"(v));
    return r;
}
__device__ __forceinline__ void fma2(unsigned long long& d,
                                     unsigned long long a, unsigned long long b) {
    asm("fma.rn.f32x2 %0, %1, %2, %0;" : "+l"(d) : "l"(a), "l"(b));
}
__device__ __forceinline__ void unpk(unsigned long long p, float& lo, float& hi) {
    asm("mov.b64 {%0, %1}, %2;" : "=f"(lo), "=f"(hi) : "l"(p));
}

// ---------------- weight packing: w[co][ci][9] -> wpair[p][cp][ci][k(10)x2] ----------------
__global__ void pack_weights(const float* __restrict__ w0, const float* __restrict__ w1,
                             const float* __restrict__ w2, const float* __restrict__ w3)
{
    int idx = blockIdx.x * blockDim.x + threadIdx.x;   // (p, cp, ci)
    if (idx >= 4 * 64 * C_) return;
    int p  = idx / (64 * C_);
    int r  = idx % (64 * C_);
    int cp = r / C_;
    int ci = r % C_;
    const float* w = (p == 0 ? w0 : p == 1 ? w1 : p == 2 ? w2 : w3);
    const float* a = w + ((size_t)(2 * cp)     * C_ + ci) * KS;
    const float* b = w + ((size_t)(2 * cp + 1) * C_ + ci) * KS;
    float* dst = g_wpair + (size_t)idx * 20;
    #pragma unroll
    for (int k = 0; k < 9; k++) { dst[2 * k] = a[k]; dst[2 * k + 1] = b[k]; }
    dst[18] = 0.f; dst[19] = 0.f;
}

// ---------------- 32x32 tiled transpose of [R x Ccols] planes ----------------
__global__ void transpose_planes(const float* __restrict__ src, float* __restrict__ dst,
                                 int R, int Ccols)
{
    __shared__ float t[32][33];
    size_t plane = (size_t)blockIdx.z * R * Ccols;
    int x  = blockIdx.x * 32 + threadIdx.x;
    int y0 = blockIdx.y * 32 + threadIdx.y;
    #pragma unroll
    for (int j = 0; j < 32; j += 8)
        t[threadIdx.y + j][threadIdx.x] = src[plane + (size_t)(y0 + j) * Ccols + x];
    __syncthreads();
    int xo = blockIdx.y * 32 + threadIdx.x;
    int yo = blockIdx.x * 32 + threadIdx.y;
    #pragma unroll
    for (int j = 0; j < 32; j += 8)
        dst[plane + (size_t)(yo + j) * R + xo] = t[threadIdx.x][threadIdx.y + j];
}

// ---------------- one scan step: y[cur] += relu(conv1d(y[prev])) ----------------
// micro-tile: 2 co (packed f32x2) x UL l per thread. NTH = 8 lgroups * 8 copairs = 64.
template<int TL, int UL>
__global__ __launch_bounds__(64) void scnn_step(
    float* __restrict__ y, const float* __restrict__ wp,
    int base_cur, int base_prev, int L)
{
    constexpr int NTH    = 64;
    constexpr int ROWLEN = TL + 2 * PAD;
    static_assert(TL / UL == 8, "8 l-groups required");

    extern __shared__ float smem[];
    float* ps = smem;                     // [C_][ROWLEN]
    float* ws = smem + C_ * ROWLEN;       // [CPB][WPS]

    const int b   = blockIdx.z;
    const int cp0 = blockIdx.y * CPB;     // first co-pair
    const int l0  = blockIdx.x * TL;
    const int tid = threadIdx.x;
    const size_t bbase = (size_t)b * C_ * STRIDE_C;

    // ---- stage prev row (aligned main + halo), shift-only indexing ----
    {
        const float* yprevb = y + bbase + base_prev;
        constexpr int JV = TL / 4;
        #pragma unroll 1
        for (int idx = tid; idx < C_ * JV; idx += NTH) {
            int ci = idx / JV;            // JV power of 2 -> shift
            int jv = idx & (JV - 1);
            float4 v = *(const float4*)(yprevb + (size_t)ci * STRIDE_C + l0 + jv * 4);
            *(float4*)&ps[ci * ROWLEN + PAD + jv * 4] = v;
        }
        #pragma unroll 1
        for (int idx = tid; idx < C_ * 8; idx += NTH) {
            int ci = idx >> 3;
            int j  = idx & 7;
            int gl, so;
            if (j < 4) { gl = l0 - 4 + j;      so = j; }
            else       { gl = l0 + TL + j - 4; so = PAD + TL + j - 4; }
            float v = 0.0f;
            if (gl >= 0 && gl < L) v = yprevb[(size_t)ci * STRIDE_C + gl];
            ps[ci * ROWLEN + so] = v;
        }
    }

    const int lg   = tid & 7;
    const int cog  = tid >> 3;            // co-pair within block
    const int lloc = lg * UL;

    unsigned long long acc2[UL];
    #pragma unroll
    for (int i = 0; i < UL; i++) acc2[i] = 0ull;

    const float4* wsrc4 = (const float4*)(wp + (size_t)cp0 * (C_ * 20));

    #pragma unroll 1
    for (int cb = 0; cb < C_ / CI_CHUNK; cb++) {
        __syncthreads();
        // stage interleaved weight chunk: 8 copairs x 32 ci x 20 floats
        #pragma unroll
        for (int cpl = 0; cpl < CPB; cpl++) {
            const float4* s = wsrc4 + ((size_t)cpl * C_ + cb * CI_CHUNK) * 5;
            float4* d = (float4*)&ws[cpl * WPS];
            #pragma unroll 1
            for (int i = tid; i < CI_CHUNK * 5; i += NTH)
                d[i] = s[i];
        }
        __syncthreads();

        const float* psrow = ps + (cb * CI_CHUNK) * ROWLEN + lloc;
        const float* wrow  = ws + cog * WPS;

        #pragma unroll 4
        for (int ci = 0; ci < CI_CHUNK; ci++) {
            // pv window: UL+8 floats
            float pv[UL + 8];
            const float* pr = psrow + ci * ROWLEN;
            if (UL == 4) {
                float4 a = *(const float4*)(pr + 0);
                float4 c = *(const float4*)(pr + 4);
                float4 e = *(const float4*)(pr + 8);
                pv[0]=a.x; pv[1]=a.y; pv[2]=a.z; pv[3]=a.w;
                pv[4]=c.x; pv[5]=c.y; pv[6]=c.z; pv[7]=c.w;
                pv[8]=e.x; pv[9]=e.y; pv[10]=e.z; pv[11]=e.w;
            } else {
                #pragma unroll
                for (int i = 0; i < UL + 8; i += 2) {
                    float2 p = *(const float2*)(pr + i);
                    pv[i] = p.x; pv[i + 1] = p.y;
                }
            }

            // weight pairs (co_even, co_odd) for k=0..8 (+zero pad k=9)
            const unsigned long long* wr = (const unsigned long long*)(wrow + ci * 20);
            ulonglong2 wab = *(const ulonglong2*)(wr + 0);   // k0,k1
            ulonglong2 wcd = *(const ulonglong2*)(wr + 2);   // k2,k3
            ulonglong2 wef = *(const ulonglong2*)(wr + 4);   // k4,k5
            ulonglong2 wgh = *(const ulonglong2*)(wr + 6);   // k6,k7
            unsigned long long wi = wr[8];                   // k8
            unsigned long long wk[9] = {wab.x, wab.y, wcd.x, wcd.y,
                                        wef.x, wef.y, wgh.x, wgh.y, wi};

            // broadcast-pack pv into f32x2
            unsigned long long q[UL + 8];
            #pragma unroll
            for (int j = 0; j < UL + 8; j++) q[j] = pk2(pv[j]);

            #pragma unroll
            for (int k = 0; k < KS; k++)
                #pragma unroll
                for (int il = 0; il < UL; il++)
                    fma2(acc2[il], wk[k], q[il + k]);
        }
    }

    // ---- epilogue: y_cur += relu(acc) for both co lanes ----
    const int co = cp0 * 2 + cog * 2;
    float* yo0 = y + bbase + (size_t)co * STRIDE_C + base_cur + l0 + lloc;
    float* yo1 = yo0 + STRIDE_C;
    float lo[UL], hi[UL];
    #pragma unroll
    for (int il = 0; il < UL; il++) unpk(acc2[il], lo[il], hi[il]);

    if (UL == 4) {
        float4 o0 = *(float4*)yo0;
        float4 o1 = *(float4*)yo1;
        o0.x += fmaxf(lo[0], 0.f); o0.y += fmaxf(lo[1], 0.f);
        o0.z += fmaxf(lo[2], 0.f); o0.w += fmaxf(lo[3], 0.f);
        o1.x += fmaxf(hi[0], 0.f); o1.y += fmaxf(hi[1], 0.f);
        o1.z += fmaxf(hi[2], 0.f); o1.w += fmaxf(hi[3], 0.f);
        *(float4*)yo0 = o0;
        *(float4*)yo1 = o1;
    } else {
        float2 o0 = *(float2*)yo0;
        float2 o1 = *(float2*)yo1;
        o0.x += fmaxf(lo[0], 0.f); o0.y += fmaxf(lo[1], 0.f);
        o1.x += fmaxf(hi[0], 0.f); o1.y += fmaxf(hi[1], 0.f);
        *(float2*)yo0 = o0;
        *(float2*)yo1 = o1;
    }
}

extern "C" void kernel_launch(void* const* d_in, const int* in_sizes, int n_in,
                              void* d_out, int out_size)
{
    const float* x    = (const float*)d_in[0];
    const float* w_ud = (const float*)d_in[1];
    const float* w_du = (const float*)d_in[2];
    const float* w_lr = (const float*)d_in[3];
    const float* w_rl = (const float*)d_in[4];
    float* y = (float*)d_out;

    float* yt;  cudaGetSymbolAddress((void**)&yt, g_yt);
    float* wp;  cudaGetSymbolAddress((void**)&wp, g_wpair);

    const int SMEM_V = (C_ * (32 + 8) + CPB * WPS) * 4;   // 41088 B
    const int SMEM_H = (C_ * (16 + 8) + CPB * WPS) * 4;   // 32896 B
    cudaFuncSetAttribute((const void*)scnn_step<32,4>,
                         cudaFuncAttributeMaxDynamicSharedMemorySize, SMEM_V);
    cudaFuncSetAttribute((const void*)scnn_step<16,2>,
                         cudaFuncAttributeMaxDynamicSharedMemorySize, SMEM_H);

    pack_weights<<<(4 * 64 * C_ + 127) / 128, 128>>>(w_ud, w_du, w_lr, w_rl);
    cudaMemcpyAsync(y, x, (size_t)out_size * sizeof(float), cudaMemcpyDeviceToDevice);

    const int WOFF = 64 * C_ * 20;

    // vertical passes: scan H, conv along W. grid 8x8x8 = 512 blocks x 2 warps
    dim3 gridV(W_ / 32, C_ / TCO, B_);
    for (int h = 1; h < H_; h++)
        scnn_step<32,4><<<gridV, 64, SMEM_V>>>(y, wp + 0 * WOFF, h * W_, (h - 1) * W_, W_);
    for (int h = H_ - 2; h >= 0; h--)
        scnn_step<32,4><<<gridV, 64, SMEM_V>>>(y, wp + 1 * WOFF, h * W_, (h + 1) * W_, W_);

    // transpose y[B,C,H,W] -> yt[B,C,W,H]
    {
        dim3 g(W_ / 32, H_ / 32, B_ * C_);
        transpose_planes<<<g, dim3(32, 8)>>>(y, yt, H_, W_);
    }

    // horizontal passes on yt: scan W, conv along H. grid 8x8x8 = 512 blocks x 2 warps
    dim3 gridH(H_ / 16, C_ / TCO, B_);
    for (int wi = 1; wi < W_; wi++)
        scnn_step<16,2><<<gridH, 64, SMEM_H>>>(yt, wp + 2 * WOFF, wi * H_, (wi - 1) * H_, H_);
    for (int wi = W_ - 2; wi >= 0; wi--)
        scnn_step<16,2><<<gridH, 64, SMEM_H>>>(yt, wp + 3 * WOFF, wi * H_, (wi + 1) * H_, H_);

    // transpose back yt[B,C,W,H] -> y[B,C,H,W]
    {
        dim3 g(H_ / 32, W_ / 32, B_ * C_);
        transpose_planes<<<g, dim3(32, 8)>>>(yt, y, W_, H_);
    }
}

// round 7
// speedup vs baseline: 1.5556x; 1.5556x over previous
#include <cuda_runtime.h>

#define C_   128
#define H_   128
#define W_   256
#define B_   8
#define KS   9
#define PAD  4
#define TCO  16
#define CI_CHUNK 16
#define WSS  (CI_CHUNK*12 + 4)       // 196 floats/co row; 196%32=4 -> conflict-free
#define WBUF (TCO * WSS)             // 3136 floats per buffer
#define STRIDE_C (H_*W_)

__device__ float g_yt[(size_t)B_ * C_ * H_ * W_];     // transposed tensor scratch
__device__ float g_wpad[4 * C_ * C_ * 12];            // padded weights

// ---- cp.async helpers ----
__device__ __forceinline__ void cpa16(void* dst, const void* src) {
    unsigned sd = (unsigned)__cvta_generic_to_shared(dst);
    asm volatile("cp.async.ca.shared.global [%0], [%1], 16;\n" :: "r"(sd), "l"(src));
}
#define CPA_COMMIT()  asm volatile("cp.async.commit_group;\n" ::: "memory")
#define CPA_WAIT(n)   asm volatile("cp.async.wait_group %0;\n" :: "n"(n) : "memory")

// ---------------- weight padding: w[co][ci][9] -> wpad[p][co][ci][12] ----------------
__global__ void pad_weights(const float* __restrict__ w0, const float* __restrict__ w1,
                            const float* __restrict__ w2, const float* __restrict__ w3)
{
    int row = blockIdx.x * blockDim.x + threadIdx.x;
    if (row >= 4 * C_ * C_) return;
    int p  = row / (C_ * C_);
    int rc = row % (C_ * C_);
    const float* src = (p == 0 ? w0 : p == 1 ? w1 : p == 2 ? w2 : w3) + rc * KS;
    float* dst = g_wpad + (size_t)row * 12;
    #pragma unroll
    for (int k = 0; k < 9; k++) dst[k] = src[k];
    dst[9] = 0.f; dst[10] = 0.f; dst[11] = 0.f;
}

// ---------------- 32x32 tiled transpose of [R x Ccols] planes ----------------
__global__ void transpose_planes(const float* __restrict__ src, float* __restrict__ dst,
                                 int R, int Ccols)
{
    __shared__ float t[32][33];
    size_t plane = (size_t)blockIdx.z * R * Ccols;
    int x  = blockIdx.x * 32 + threadIdx.x;
    int y0 = blockIdx.y * 32 + threadIdx.y;
    #pragma unroll
    for (int j = 0; j < 32; j += 8)
        t[threadIdx.y + j][threadIdx.x] = src[plane + (size_t)(y0 + j) * Ccols + x];
    __syncthreads();
    int xo = blockIdx.y * 32 + threadIdx.x;
    int yo = blockIdx.x * 32 + threadIdx.y;
    #pragma unroll
    for (int j = 0; j < 32; j += 8)
        dst[plane + (size_t)(yo + j) * R + xo] = t[threadIdx.x][threadIdx.y + j];
}

// ---------------- one scan step: y[cur] += relu(conv1d(y[prev])) ----------------
// micro-tile: 1 co x UL l per thread; 8 l-groups x 16 co = 128 threads.
// Weight chunks double-buffered via cp.async; prefetch cb+1 overlaps compute cb.
template<int TL, int UL>
__global__ __launch_bounds__(128) void scnn_step(
    float* __restrict__ y, const float* __restrict__ wp,
    int base_cur, int base_prev, int L)
{
    constexpr int NTH    = 128;
    constexpr int ROWLEN = TL + 2 * PAD;
    constexpr int NCH    = C_ / CI_CHUNK;          // 8
    static_assert(TL / UL == 8, "8 l-groups required");

    extern __shared__ float smem[];
    float* ps = smem;                     // [C_][ROWLEN]
    float* ws = smem + C_ * ROWLEN;       // [2][TCO][WSS]

    const int b   = blockIdx.z;
    const int co0 = blockIdx.y * TCO;
    const int l0  = blockIdx.x * TL;
    const int tid = threadIdx.x;
    const size_t bbase = (size_t)b * C_ * STRIDE_C;

    const float4* wsrc4 = (const float4*)(wp + (size_t)co0 * (C_ * 12));
    const int wco = tid >> 3;             // staging co (8 threads per co)
    const int wr0 = tid & 7;

    // ---- async stage: ps main + weight chunk 0 (group 0) ----
    {
        const float* yprevb = y + bbase + base_prev;
        constexpr int JV = TL / 4;
        #pragma unroll
        for (int idx = tid; idx < C_ * JV; idx += NTH) {
            int ci = idx / JV;            // JV power of 2 -> shift
            int jv = idx & (JV - 1);
            cpa16(&ps[ci * ROWLEN + PAD + jv * 4],
                  yprevb + (size_t)ci * STRIDE_C + l0 + jv * 4);
        }
        {
            const float4* s = wsrc4 + (size_t)wco * (C_ * 3);
            float4* d = (float4*)&ws[wco * WSS];
            #pragma unroll
            for (int i = 0; i < (CI_CHUNK * 3) / 8; i++)
                cpa16(d + wr0 + i * 8, s + wr0 + i * 8);
        }
        CPA_COMMIT();

        // halo: 4 left + 4 right per ci, bounds-checked (plain LDG/STS)
        #pragma unroll 1
        for (int idx = tid; idx < C_ * 8; idx += NTH) {
            int ci = idx >> 3;
            int j  = idx & 7;
            int gl, so;
            if (j < 4) { gl = l0 - 4 + j;      so = j; }
            else       { gl = l0 + TL + j - 4; so = PAD + TL + j - 4; }
            float v = 0.0f;
            if (gl >= 0 && gl < L) v = yprevb[(size_t)ci * STRIDE_C + gl];
            ps[ci * ROWLEN + so] = v;
        }
    }

    const int lg   = tid & 7;
    const int cog  = tid >> 3;
    const int lloc = lg * UL;

    float acc[UL];
    #pragma unroll
    for (int i = 0; i < UL; i++) acc[i] = 0.f;

    #pragma unroll 1
    for (int cb = 0; cb < NCH; cb++) {
        // prefetch next weight chunk into other buffer
        if (cb + 1 < NCH) {
            const float4* s = wsrc4 + (size_t)wco * (C_ * 3) + (cb + 1) * (CI_CHUNK * 3);
            float4* d = (float4*)&ws[((cb + 1) & 1) * WBUF + wco * WSS];
            #pragma unroll
            for (int i = 0; i < (CI_CHUNK * 3) / 8; i++)
                cpa16(d + wr0 + i * 8, s + wr0 + i * 8);
            CPA_COMMIT();
            CPA_WAIT(1);
        } else {
            CPA_WAIT(0);
        }
        __syncthreads();

        const float* psrow = ps + (cb * CI_CHUNK) * ROWLEN + lloc;
        const float* wrow  = ws + (cb & 1) * WBUF + cog * WSS;

        // register-pipelined: load ci+1 while FMAing ci
        float pv[UL + 8], npv[UL + 8];
        float wv[12], nwv[12];
        if (UL == 4) {
            float4 a = *(const float4*)(psrow + 0);
            float4 c = *(const float4*)(psrow + 4);
            float4 e = *(const float4*)(psrow + 8);
            pv[0]=a.x; pv[1]=a.y; pv[2]=a.z;  pv[3]=a.w;
            pv[4]=c.x; pv[5]=c.y; pv[6]=c.z;  pv[7]=c.w;
            pv[8]=e.x; pv[9]=e.y; pv[10]=e.z; pv[11]=e.w;
        } else {
            #pragma unroll
            for (int i = 0; i < UL + 8; i += 2) {
                float2 p = *(const float2*)(psrow + i);
                pv[i] = p.x; pv[i + 1] = p.y;
            }
        }
        {
            float4 a = *(const float4*)(wrow + 0);
            float4 c = *(const float4*)(wrow + 4);
            float4 e = *(const float4*)(wrow + 8);
            wv[0]=a.x; wv[1]=a.y; wv[2]=a.z; wv[3]=a.w;
            wv[4]=c.x; wv[5]=c.y; wv[6]=c.z; wv[7]=c.w;
            wv[8]=e.x;
        }

        #pragma unroll
        for (int ci = 0; ci < CI_CHUNK; ci++) {
            if (ci + 1 < CI_CHUNK) {
                const float* pn = psrow + (ci + 1) * ROWLEN;
                const float* wn = wrow  + (ci + 1) * 12;
                if (UL == 4) {
                    float4 a = *(const float4*)(pn + 0);
                    float4 c = *(const float4*)(pn + 4);
                    float4 e = *(const float4*)(pn + 8);
                    npv[0]=a.x; npv[1]=a.y; npv[2]=a.z;  npv[3]=a.w;
                    npv[4]=c.x; npv[5]=c.y; npv[6]=c.z;  npv[7]=c.w;
                    npv[8]=e.x; npv[9]=e.y; npv[10]=e.z; npv[11]=e.w;
                } else {
                    #pragma unroll
                    for (int i = 0; i < UL + 8; i += 2) {
                        float2 p = *(const float2*)(pn + i);
                        npv[i] = p.x; npv[i + 1] = p.y;
                    }
                }
                float4 a = *(const float4*)(wn + 0);
                float4 c = *(const float4*)(wn + 4);
                float4 e = *(const float4*)(wn + 8);
                nwv[0]=a.x; nwv[1]=a.y; nwv[2]=a.z; nwv[3]=a.w;
                nwv[4]=c.x; nwv[5]=c.y; nwv[6]=c.z; nwv[7]=c.w;
                nwv[8]=e.x;
            }

            #pragma unroll
            for (int k = 0; k < KS; k++)
                #pragma unroll
                for (int il = 0; il < UL; il++)
                    acc[il] = fmaf(wv[k], pv[il + k], acc[il]);

            if (ci + 1 < CI_CHUNK) {
                #pragma unroll
                for (int i = 0; i < UL + 8; i++) pv[i] = npv[i];
                #pragma unroll
                for (int i = 0; i < 9; i++) wv[i] = nwv[i];
            }
        }
        __syncthreads();
    }

    // ---- epilogue: y_cur += relu(acc), vector RMW ----
    float* yo = y + bbase + (size_t)(co0 + cog) * STRIDE_C + base_cur + l0 + lloc;
    if (UL == 4) {
        float4 o = *(float4*)yo;
        o.x += fmaxf(acc[0], 0.f);
        o.y += fmaxf(acc[1], 0.f);
        o.z += fmaxf(acc[2], 0.f);
        o.w += fmaxf(acc[3], 0.f);
        *(float4*)yo = o;
    } else {
        float2 o = *(float2*)yo;
        o.x += fmaxf(acc[0], 0.f);
        o.y += fmaxf(acc[1], 0.f);
        *(float2*)yo = o;
    }
}

extern "C" void kernel_launch(void* const* d_in, const int* in_sizes, int n_in,
                              void* d_out, int out_size)
{
    const float* x    = (const float*)d_in[0];
    const float* w_ud = (const float*)d_in[1];
    const float* w_du = (const float*)d_in[2];
    const float* w_lr = (const float*)d_in[3];
    const float* w_rl = (const float*)d_in[4];
    float* y = (float*)d_out;

    float* yt;  cudaGetSymbolAddress((void**)&yt, g_yt);
    float* wp;  cudaGetSymbolAddress((void**)&wp, g_wpad);

    const int SMEM_V = (C_ * (32 + 8) + 2 * WBUF) * 4;   // 45568 B
    const int SMEM_H = (C_ * (16 + 8) + 2 * WBUF) * 4;   // 37376 B
    cudaFuncSetAttribute((const void*)scnn_step<32,4>,
                         cudaFuncAttributeMaxDynamicSharedMemorySize, SMEM_V);
    cudaFuncSetAttribute((const void*)scnn_step<16,2>,
                         cudaFuncAttributeMaxDynamicSharedMemorySize, SMEM_H);

    pad_weights<<<(4 * C_ * C_ + 127) / 128, 128>>>(w_ud, w_du, w_lr, w_rl);
    cudaMemcpyAsync(y, x, (size_t)out_size * sizeof(float), cudaMemcpyDeviceToDevice);

    const int WOFF = C_ * C_ * 12;

    // vertical passes: scan H, conv along W. grid 8x8x8 = 512 blocks x 4 warps
    dim3 gridV(W_ / 32, C_ / TCO, B_);
    for (int h = 1; h < H_; h++)
        scnn_step<32,4><<<gridV, 128, SMEM_V>>>(y, wp + 0 * WOFF, h * W_, (h - 1) * W_, W_);
    for (int h = H_ - 2; h >= 0; h--)
        scnn_step<32,4><<<gridV, 128, SMEM_V>>>(y, wp + 1 * WOFF, h * W_, (h + 1) * W_, W_);

    // transpose y[B,C,H,W] -> yt[B,C,W,H]
    {
        dim3 g(W_ / 32, H_ / 32, B_ * C_);
        transpose_planes<<<g, dim3(32, 8)>>>(y, yt, H_, W_);
    }

    // horizontal passes on yt: scan W, conv along H. grid 8x8x8 = 512 blocks x 4 warps
    dim3 gridH(H_ / 16, C_ / TCO, B_);
    for (int wi = 1; wi < W_; wi++)
        scnn_step<16,2><<<gridH, 128, SMEM_H>>>(yt, wp + 2 * WOFF, wi * H_, (wi - 1) * H_, H_);
    for (int wi = W_ - 2; wi >= 0; wi--)
        scnn_step<16,2><<<gridH, 128, SMEM_H>>>(yt, wp + 3 * WOFF, wi * H_, (wi + 1) * H_, H_);

    // transpose back yt[B,C,W,H] -> y[B,C,H,W]
    {
        dim3 g(H_ / 32, W_ / 32, B_ * C_);
        transpose_planes<<<g, dim3(32, 8)>>>(yt, y, W_, H_);
    }
}

// round 10
// speedup vs baseline: 2.6894x; 1.7289x over previous
#include <cuda_runtime.h>

#define C_   128
#define H_   128
#define W_   256
#define B_   8
#define KS   9
#define STRIDE_C (H_*W_)
#define WST  1156        // weight smem row stride (floats); 1156%32=4 -> co banks distinct
#define NBPB 32          // blocks per batch (4 l-tiles x 8 co-tiles)

__device__ float    g_yt[(size_t)B_ * C_ * H_ * W_];   // transposed tensor scratch
__device__ unsigned g_flags[4 * B_ * 256];              // per-pass, per-batch, per-step

// ---- cp.async helpers ----
__device__ __forceinline__ void cpa16(void* dst, const void* src) {
    unsigned sd = (unsigned)__cvta_generic_to_shared(dst);
    asm volatile("cp.async.ca.shared.global [%0], [%1], 16;\n" :: "r"(sd), "l"(src));
}
#define CPA_COMMIT()  asm volatile("cp.async.commit_group;\n" ::: "memory")
#define CPA_WAIT0()   asm volatile("cp.async.wait_group 0;\n" ::: "memory")

// ---------------- 32x32 tiled transpose of [R x Ccols] planes ----------------
__global__ void transpose_planes(const float* __restrict__ src, float* __restrict__ dst,
                                 int R, int Ccols)
{
    __shared__ float t[32][33];
    size_t plane = (size_t)blockIdx.z * R * Ccols;
    int x  = blockIdx.x * 32 + threadIdx.x;
    int y0 = blockIdx.y * 32 + threadIdx.y;
    #pragma unroll
    for (int j = 0; j < 32; j += 8)
        t[threadIdx.y + j][threadIdx.x] = src[plane + (size_t)(y0 + j) * Ccols + x];
    __syncthreads();
    int xo = blockIdx.y * 32 + threadIdx.x;
    int yo = blockIdx.x * 32 + threadIdx.y;
    #pragma unroll
    for (int j = 0; j < 32; j += 8)
        dst[plane + (size_t)(yo + j) * R + xo] = t[threadIdx.x][threadIdx.y + j];
}

// ---------------- persistent scan pass ----------------
// One kernel runs ALL steps of one directional pass.
// Block = (l-tile, co-tile, batch). Per-batch flag barrier between steps.
// Micro-tile: 1 co x 8 l per thread; ci split SPLIT ways (reduction via smem).
template<int TL, int SPLIT>
__global__ __launch_bounds__(256, 2) void scan_pass(
    float* __restrict__ y, const float* __restrict__ wg,
    unsigned* __restrict__ flags, int L, int S, int dir)
{
    constexpr int LG     = TL / 8;          // l-groups (8 or 4)
    constexpr int ROWLEN = TL + 8;
    constexpr int CIPG   = C_ / SPLIT;      // ci per split group
    constexpr int TPG    = LG * 16;         // threads per split group
    constexpr int NF4    = C_ * TL / 4;     // main-stage float4 count
    constexpr int JV     = TL / 4;          // float4 per row main (16 or 8)
    constexpr int LGSH   = (LG == 8) ? 3 : 2;

    extern __shared__ float smem[];
    float* ps  = smem;                      // [128][ROWLEN]
    float* wsm = smem + C_ * ROWLEN;        // [16][WST]

    const int tid = threadIdx.x;
    const int b   = blockIdx.z;
    const int co0 = blockIdx.y * 16;
    const int l0  = blockIdx.x * TL;
    const size_t bbase = (size_t)b * C_ * STRIDE_C;
    unsigned* flag = flags + b * 256;

    // ---- load this block's weights ONCE: 16 co x 1152 floats ----
    {
        const float4* src = (const float4*)(wg + (size_t)co0 * (C_ * KS));
        #pragma unroll 1
        for (int idx = tid; idx < 16 * 288; idx += 256) {
            int row = idx / 288;
            int r4  = idx - row * 288;
            cpa16(&wsm[row * WST + r4 * 4], src + row * 288 + r4);
        }
        CPA_COMMIT(); CPA_WAIT0();
    }
    __syncthreads();

    const int lg   = tid & (LG - 1);
    const int co   = (tid >> LGSH) & 15;
    const int g    = tid >> (LGSH + 4);
    const int lloc = lg * 8;
    const int ci0  = g * CIPG;
    const int slot = tid & (TPG - 1);
    const bool g0  = (g == 0);

    #pragma unroll 1
    for (int s = 1; s < S; s++) {
        const int cur  = (dir > 0) ? s : (S - 1 - s);
        const int prev = cur - dir;

        // ---- wait until all 32 same-batch blocks finished step s-1 ----
        if (s > 1 && tid == 0) {
            const unsigned* f = flag + (s - 1);
            unsigned v;
            do {
                asm volatile("ld.acquire.gpu.u32 %0, [%1];" : "=r"(v) : "l"(f));
            } while (v < NBPB);
        }
        __syncthreads();   // also protects ps/scratch reuse across iterations

        // ---- stage prev row into ps (main via cp.async, halo guarded) ----
        {
            const float* yprev = y + bbase + (size_t)prev * L;
            #pragma unroll
            for (int i = 0; i < NF4 / 256; i++) {
                int idx = tid + i * 256;
                int ci  = idx / JV;               // JV power of 2 -> shift
                int jv  = idx & (JV - 1);
                cpa16(&ps[ci * ROWLEN + 4 + jv * 4],
                      yprev + (size_t)ci * STRIDE_C + l0 + jv * 4);
            }
            CPA_COMMIT();
            #pragma unroll
            for (int i = 0; i < 4; i++) {
                int idx = tid + i * 256;
                int ci  = idx >> 3;
                int j   = idx & 7;
                int gl, so;
                if (j < 4) { gl = l0 - 4 + j;       so = j; }
                else       { gl = l0 + TL + j - 4;  so = 4 + TL + j - 4; }
                float v = 0.0f;
                if (gl >= 0 && gl < L) v = yprev[(size_t)ci * STRIDE_C + gl];
                ps[ci * ROWLEN + so] = v;
            }
            CPA_WAIT0();
        }
        __syncthreads();

        // ---- compute: this split group's ci range ----
        float acc[8];
        #pragma unroll
        for (int i = 0; i < 8; i++) acc[i] = 0.f;
        {
            const float* prow = ps + ci0 * ROWLEN + lloc;
            const float* wrow = wsm + co * WST + ci0 * 9;
            #pragma unroll 2
            for (int ci = 0; ci < CIPG; ci++) {
                const float* p = prow + ci * ROWLEN;
                float4 a  = *(const float4*)(p + 0);
                float4 b4 = *(const float4*)(p + 4);
                float4 c4 = *(const float4*)(p + 8);
                float4 d4 = *(const float4*)(p + 12);
                float pv[16] = {a.x,a.y,a.z,a.w,  b4.x,b4.y,b4.z,b4.w,
                                c4.x,c4.y,c4.z,c4.w, d4.x,d4.y,d4.z,d4.w};
                const float* wr = wrow + ci * 9;
                float wv[9];
                #pragma unroll
                for (int k = 0; k < 9; k++) wv[k] = wr[k];
                #pragma unroll
                for (int k = 0; k < 9; k++)
                    #pragma unroll
                    for (int il = 0; il < 8; il++)
                        acc[il] = fmaf(wv[k], pv[il + k], acc[il]);
            }
        }

        // ---- cross-group reduction (scratch overlays ps, now consumed) ----
        __syncthreads();
        float* sc = ps;
        if (!g0) {
            float* d = sc + ((g - 1) * TPG + slot) * 8;
            #pragma unroll
            for (int i = 0; i < 8; i++) d[i] = acc[i];
        }
        __syncthreads();

        if (g0) {
            #pragma unroll
            for (int gg = 1; gg < SPLIT; gg++) {
                const float* d = sc + ((gg - 1) * TPG + slot) * 8;
                #pragma unroll
                for (int i = 0; i < 8; i++) acc[i] += d[i];
            }
            // RMW: y[cur] += relu(acc)
            float* yo = y + bbase + (size_t)(co0 + co) * STRIDE_C
                          + (size_t)cur * L + l0 + lloc;
            float4 o0 = *(float4*)yo;
            float4 o1 = *(float4*)(yo + 4);
            o0.x += fmaxf(acc[0], 0.f); o0.y += fmaxf(acc[1], 0.f);
            o0.z += fmaxf(acc[2], 0.f); o0.w += fmaxf(acc[3], 0.f);
            o1.x += fmaxf(acc[4], 0.f); o1.y += fmaxf(acc[5], 0.f);
            o1.z += fmaxf(acc[6], 0.f); o1.w += fmaxf(acc[7], 0.f);
            *(float4*)yo       = o0;
            *(float4*)(yo + 4) = o1;
            __threadfence();
        }
        __syncthreads();
        if (tid == 0)
            asm volatile("red.release.gpu.global.add.u32 [%0], %1;"
                         :: "l"(flag + s), "r"(1u));
    }
}

extern "C" void kernel_launch(void* const* d_in, const int* in_sizes, int n_in,
                              void* d_out, int out_size)
{
    const float* x    = (const float*)d_in[0];
    const float* w_ud = (const float*)d_in[1];
    const float* w_du = (const float*)d_in[2];
    const float* w_lr = (const float*)d_in[3];
    const float* w_rl = (const float*)d_in[4];
    float* y = (float*)d_out;

    float*    yt;  cudaGetSymbolAddress((void**)&yt, g_yt);
    unsigned* fl;  cudaGetSymbolAddress((void**)&fl, g_flags);

    const int SMEM_V = (C_ * (64 + 8) + 16 * WST) * 4;   // 110848 B
    const int SMEM_H = (C_ * (32 + 8) + 16 * WST) * 4;   //  94464 B
    cudaFuncSetAttribute((const void*)scan_pass<64,2>,
                         cudaFuncAttributeMaxDynamicSharedMemorySize, SMEM_V);
    cudaFuncSetAttribute((const void*)scan_pass<32,4>,
                         cudaFuncAttributeMaxDynamicSharedMemorySize, SMEM_H);

    // reset flags + init y = x
    cudaMemsetAsync(fl, 0, 4 * B_ * 256 * sizeof(unsigned));
    cudaMemcpyAsync(y, x, (size_t)out_size * sizeof(float), cudaMemcpyDeviceToDevice);

    dim3 grid(4, 8, B_);   // 256 blocks, all co-resident (2/SM)

    // vertical passes on y: scan H (S=128), rows along W (L=256)
    scan_pass<64,2><<<grid, 256, SMEM_V>>>(y, w_ud, fl + 0 * B_ * 256, W_, H_, +1);
    scan_pass<64,2><<<grid, 256, SMEM_V>>>(y, w_du, fl + 1 * B_ * 256, W_, H_, -1);

    // transpose y[B,C,H,W] -> yt[B,C,W,H]
    {
        dim3 g(W_ / 32, H_ / 32, B_ * C_);
        transpose_planes<<<g, dim3(32, 8)>>>(y, yt, H_, W_);
    }

    // horizontal passes on yt: scan W (S=256), rows along H (L=128)
    scan_pass<32,4><<<grid, 256, SMEM_H>>>(yt, w_lr, fl + 2 * B_ * 256, H_, W_, +1);
    scan_pass<32,4><<<grid, 256, SMEM_H>>>(yt, w_rl, fl + 3 * B_ * 256, H_, W_, -1);

    // transpose back yt[B,C,W,H] -> y[B,C,H,W]
    {
        dim3 g(H_ / 32, W_ / 32, B_ * C_);
        transpose_planes<<<g, dim3(32, 8)>>>(yt, y, W_, H_);
    }
}